// round 17
// baseline (speedup 1.0000x reference)
#include <cuda_runtime.h>
#include <cuda_bf16.h>
#include <cuda_fp16.h>
#include <math.h>

// ---------------- problem constants ----------------
#define B_    2
#define T_    64
#define N_    4096
#define HOR_  24
#define C_    16
#define HID_  32
#define BD_   8
#define HEADS_ 4
#define HD_   8
#define BH_   (B_*HEADS_)      // 8
#define LOG2E 1.4426950408889634f
#define INV_SQRT8 0.35355339059327373f
#define KSPLIT 4

// ---------------- scratch (device globals; no allocation) ----------------
__device__ __align__(16) __nv_bfloat16 d_Qh[BH_ * N_ * 16];
__device__ __align__(16) __nv_bfloat16 d_Ql[BH_ * N_ * 16];
__device__ __align__(16) __nv_bfloat16 d_Kh[BH_ * N_ * 16];
__device__ __align__(16) __nv_bfloat16 d_Kl[BH_ * N_ * 16];
__device__ __align__(16) __half d_Vh[BH_ * N_ * 8];
__device__ float d_patt[KSPLIT * BH_ * N_ * 8];   // unnormalized partial O
__device__ float d_pl[KSPLIT * BH_ * N_];         // partial row sums

__device__ __forceinline__ float elu1(float x) {
    return x > 0.f ? x + 1.f : __expf(x);
}
__device__ __forceinline__ void bsplit(float x, __nv_bfloat16& hi, __nv_bfloat16& lo) {
    __nv_bfloat16 h = __float2bfloat16(x);
    hi = h;
    lo = __float2bfloat16(x - __bfloat162float(h));
}

// bf16 m16n8k16 mma, fp32 accumulate
__device__ __forceinline__ void mma16816(float d[4], const unsigned a[4],
                                         const unsigned b[2], const float c[4]) {
    asm volatile(
        "mma.sync.aligned.m16n8k16.row.col.f32.bf16.bf16.f32 "
        "{%0,%1,%2,%3}, {%4,%5,%6,%7}, {%8,%9}, {%10,%11,%12,%13};"
        : "=f"(d[0]), "=f"(d[1]), "=f"(d[2]), "=f"(d[3])
        : "r"(a[0]), "r"(a[1]), "r"(a[2]), "r"(a[3]),
          "r"(b[0]), "r"(b[1]),
          "f"(c[0]), "f"(c[1]), "f"(c[2]), "f"(c[3]));
}
// fp16 m16n8k16 mma, fp32 accumulate
__device__ __forceinline__ void mma16816h(float d[4], const unsigned a[4],
                                          const unsigned b[2], const float c[4]) {
    asm volatile(
        "mma.sync.aligned.m16n8k16.row.col.f32.f16.f16.f32 "
        "{%0,%1,%2,%3}, {%4,%5,%6,%7}, {%8,%9}, {%10,%11,%12,%13};"
        : "=f"(d[0]), "=f"(d[1]), "=f"(d[2]), "=f"(d[3])
        : "r"(a[0]), "r"(a[1]), "r"(a[2]), "r"(a[3]),
          "r"(b[0]), "r"(b[1]),
          "f"(c[0]), "f"(c[1]), "f"(c[2]), "f"(c[3]));
}
// pack two fp32 into fp16x2: lo half = x, hi half = y
__device__ __forceinline__ unsigned packh2(float x, float y) {
    unsigned r;
    asm("cvt.rn.f16x2.f32 %0, %1, %2;" : "=r"(r) : "f"(y), "f"(x));
    return r;
}
__device__ __forceinline__ unsigned ex2h2(unsigned s) {
    unsigned r;
    asm("ex2.approx.f16x2 %0, %1;" : "=r"(r) : "r"(s));
    return r;
}

// =====================================================================
// Kernel A: conv -> p1 -> p2 -> qkv -> split Q'/K' (bf16), V (fp16)
// 1 node per warp, 8 nodes/block, 1024 blocks; phase-aliased smem
// =====================================================================
#define XS_OFF  0                       // float[8][66]  = 2112 B
#define CW_OFF  2112                    // float[48]     = 192 B
#define CSH_OFF 2304                    // float[16]     = 64 B
#define P1_OFF  2368                    // float[8192]   = 32768 B (phase 1)
#define WT_OFF  2368                    // float[32*97]  = 12416 B (phase 2)
#define FS_OFF  14784                   // float[8][32]  = 1024 B  (phase 2)
#define FEAT_SMEM 35136

__global__ void __launch_bounds__(256)
feat_kernel(const float* __restrict__ x,
            const float* __restrict__ fe_w, const float* __restrict__ fe_b,
            const float* __restrict__ bn_g, const float* __restrict__ bn_b,
            const float* __restrict__ p1_w, const float* __restrict__ p1_b,
            const float* __restrict__ p2_w, const float* __restrict__ p2_b,
            const float* __restrict__ qkv_w, const float* __restrict__ qkv_b,
            const float* __restrict__ u, const float* __restrict__ v)
{
    __shared__ __align__(16) char sbuf[FEAT_SMEM];
    float* xsf  = (float*)(sbuf + XS_OFF);      // [8][66]
    float* cw   = (float*)(sbuf + CW_OFF);
    float* csh  = (float*)(sbuf + CSH_OFF);
    float* p1s  = (float*)(sbuf + P1_OFF);
    float* wt   = (float*)(sbuf + WT_OFF);
    float* fsf  = (float*)(sbuf + FS_OFF);      // [8][32]

    const int tid = threadIdx.x;
    const int blk = blockIdx.x;
    const int b   = blk >> 9;
    const int n0  = (blk & 511) << 3;

    for (int i = tid; i < 2048; i += 256)
        ((float4*)p1s)[i] = ((const float4*)p1_w)[i];
    if (tid < 48) {
        int c = tid / 3;
        float sc = bn_g[c] * rsqrtf(1.f + 1e-5f);
        cw[tid] = fe_w[tid] * sc;
    }
    if (tid < 16) {
        float sc = bn_g[tid] * rsqrtf(1.f + 1e-5f);
        csh[tid] = fe_b[tid] * sc + bn_b[tid];
    }
    for (int i = tid; i < 512; i += 256) {
        int node = i & 7, t = i >> 3;
        xsf[node * 66 + t + 1] = x[(size_t)b * T_ * N_ + (size_t)t * N_ + n0 + node];
    }
    if (tid < 8) { xsf[tid * 66] = 0.f; xsf[tid * 66 + 65] = 0.f; }
    __syncthreads();

    const int w = tid >> 5, lane = tid & 31;
    const int n = n0 + w;

    // hoist conv inputs into registers
    const float* xA = xsf + w * 66;
    const float a0 = xA[lane],      a1 = xA[lane + 1],  a2 = xA[lane + 2];
    const float a3 = xA[lane + 32], a4 = xA[lane + 33], a5 = xA[lane + 34];

    float acc[8];
#pragma unroll
    for (int j = 0; j < 8; j++) acc[j] = 0.f;

#pragma unroll
    for (int i = 0; i < 32; i++) {
        int cc = i >> 1;
        float w0 = cw[cc * 3], w1 = cw[cc * 3 + 1], w2 = cw[cc * 3 + 2], sh = csh[cc];
        float val;
        if ((i & 1) == 0)
            val = a0 * w0 + a1 * w1 + a2 * w2 + sh;
        else
            val = a3 * w0 + a4 * w1 + a5 * w2 + sh;
        val = fmaxf(val, 0.f);
        int base = i * 32 + lane;
#pragma unroll
        for (int j = 0; j < 8; j++)
            acc[j] += val * p1s[j * 1024 + base];
    }
#pragma unroll
    for (int j = 0; j < 8; j++)
#pragma unroll
        for (int off = 16; off; off >>= 1)
            acc[j] += __shfl_xor_sync(0xffffffffu, acc[j], off);

    float r1[8];
#pragma unroll
    for (int j = 0; j < 8; j++)
        r1[j] = fmaxf(acc[j] + __ldg(p1_b + j), 0.f);

    float f = __ldg(p2_b + lane);
#pragma unroll
    for (int j = 0; j < 8; j++)
        f += r1[j] * __ldg(p2_w + lane * 8 + j);

    // phase 2: p1s reads done; alias wt/fs into its region
    __syncthreads();
    for (int idx = tid; idx < 3072; idx += 256) {
        int o = idx >> 5, i = idx & 31;
        wt[i * 97 + o] = qkv_w[idx];
    }
    fsf[w * 32 + lane] = f;
    __syncthreads();

    float oq = __ldg(qkv_b + lane);
    float ok = __ldg(qkv_b + lane + 32);
    float ov = __ldg(qkv_b + lane + 64);
#pragma unroll
    for (int i = 0; i < 32; i++) {
        float fi = fsf[w * 32 + i];
        const float* wr = wt + i * 97;
        oq += fi * wr[lane];
        ok += fi * wr[lane + 32];
        ov += fi * wr[lane + 64];
    }

    const int head = lane >> 3, d = lane & 7;
    const size_t ridx = ((size_t)(b * 4 + head) * N_ + n);
    const size_t qidx = ridx * 16;
    bsplit(elu1(oq) * (LOG2E * INV_SQRT8), d_Qh[qidx + d],     d_Ql[qidx + d]);
    bsplit(u[(size_t)n * 8 + d] * LOG2E,   d_Qh[qidx + 8 + d], d_Ql[qidx + 8 + d]);
    bsplit(elu1(ok),                       d_Kh[qidx + d],     d_Kl[qidx + d]);
    bsplit(v[(size_t)d * N_ + n],          d_Kh[qidx + 8 + d], d_Kl[qidx + 8 + d]);
    d_Vh[ridx * 8 + d] = __float2half_rn(ov);
}

// =====================================================================
// Kernel B: tensor-core flash attention; QK bf16-split, softmax+PV in
// packed fp16 (ex2.approx.f16x2, P fp16, V fp16 single). split-K=4,
// 256 threads, double-buffered, one sync per tile.
// grid (N/128, BH, KSPLIT) = (32, 8, 4) = 1024 blocks
// =====================================================================
#define KTILE 128
#define NIT   ((N_ / KSPLIT) / KTILE)   // 8
#define SCLAMP 15.5f
__global__ void __launch_bounds__(256)
attn_kernel()
{
    const int bh = blockIdx.y;
    const int qbase = blockIdx.x * 128;
    const int kz = blockIdx.z;
    const int tid = threadIdx.x, w = tid >> 5, l = tid & 31;

    __shared__ __align__(16) unsigned Khl[2][KTILE * 16];   // 16 KB
    __shared__ __align__(16) unsigned Vs_[2][8 * 72];       // 4.6 KB

    const unsigned* Qh_u = (const unsigned*)d_Qh + (size_t)bh * N_ * 8;
    const unsigned* Ql_u = (const unsigned*)d_Ql + (size_t)bh * N_ * 8;
    const unsigned* Kh_u = (const unsigned*)d_Kh + (size_t)bh * N_ * 8;
    const unsigned* Kl_u = (const unsigned*)d_Kl + (size_t)bh * N_ * 8;
    const __half* Vh_g = d_Vh + (size_t)bh * N_ * 8;

    const int qr0 = qbase + w * 16 + (l >> 2);
    const int qr1 = qr0 + 8;
    const int c4 = l & 3;

    unsigned ah[4], al[4];
    ah[0] = Qh_u[qr0 * 8 + c4];     ah[1] = Qh_u[qr1 * 8 + c4];
    ah[2] = Qh_u[qr0 * 8 + c4 + 4]; ah[3] = Qh_u[qr1 * 8 + c4 + 4];
    al[0] = Ql_u[qr0 * 8 + c4];     al[1] = Ql_u[qr1 * 8 + c4];
    al[2] = Ql_u[qr0 * 8 + c4 + 4]; al[3] = Ql_u[qr1 * 8 + c4 + 4];

    float O0[4] = {0,0,0,0}, La[4] = {0,0,0,0};
    const unsigned ones2 = 0x3C003C00u;      // fp16x2 {1,1}
    unsigned bones[2] = {ones2, ones2};

    unsigned kreg[2][4];
    __half vreg[4];

    const int kkey0 = tid >> 2, kkc = tid & 3;
    const int kkey1 = (tid + 256) >> 2;
    const int vkey0 = tid >> 3, vvd = tid & 7;

    const int k0 = kz * (N_ / KSPLIT);

    auto ldg_tile = [&](int kt) {
        kreg[0][0] = Kh_u[(size_t)(kt + kkey0) * 8 + kkc];
        kreg[0][1] = Kh_u[(size_t)(kt + kkey0) * 8 + kkc + 4];
        kreg[0][2] = Kl_u[(size_t)(kt + kkey0) * 8 + kkc];
        kreg[0][3] = Kl_u[(size_t)(kt + kkey0) * 8 + kkc + 4];
        kreg[1][0] = Kh_u[(size_t)(kt + kkey1) * 8 + kkc];
        kreg[1][1] = Kh_u[(size_t)(kt + kkey1) * 8 + kkc + 4];
        kreg[1][2] = Kl_u[(size_t)(kt + kkey1) * 8 + kkc];
        kreg[1][3] = Kl_u[(size_t)(kt + kkey1) * 8 + kkc + 4];
#pragma unroll
        for (int i = 0; i < 4; i++) {
            int key = vkey0 + i * 32;
            vreg[i] = Vh_g[(size_t)(kt + key) * 8 + vvd];
        }
    };
    auto sts_tile = [&](int bb) {
        *(uint4*)&Khl[bb][kkey0 * 16 + kkc * 4] =
            make_uint4(kreg[0][0], kreg[0][1], kreg[0][2], kreg[0][3]);
        *(uint4*)&Khl[bb][kkey1 * 16 + kkc * 4] =
            make_uint4(kreg[1][0], kreg[1][1], kreg[1][2], kreg[1][3]);
        __half* Vsh = (__half*)Vs_[bb];
#pragma unroll
        for (int i = 0; i < 4; i++) {
            int key = vkey0 + i * 32;
            int j = key >> 1, half = key & 1;
            int ci = j >> 3, c4v = j & 3, hi4 = (j >> 2) & 1;
            Vsh[2 * (vvd * 72 + ci * 8 + c4v * 2 + hi4) + half] = vreg[i];
        }
    };

    ldg_tile(k0);
    sts_tile(0);
    __syncthreads();

    for (int it = 0; it < NIT; it++) {
        const int bb = it & 1;
        if (it + 1 < NIT) ldg_tile(k0 + (it + 1) * KTILE);

        const unsigned* Kb = Khl[bb];
        const unsigned* Vb = Vs_[bb];
#pragma unroll
        for (int c16 = 0; c16 < KTILE; c16 += 16) {
            float S0[4] = {0.f, 0.f, 0.f, 0.f};
            float S1[4] = {0.f, 0.f, 0.f, 0.f};

            const int kr0 = c16 + (l >> 2);
            const int kr1 = kr0 + 8;
            uint4 k0v = *(const uint4*)&Kb[kr0 * 16 + c4 * 4];
            uint4 k1v = *(const uint4*)&Kb[kr1 * 16 + c4 * 4];
            unsigned kh0[2] = {k0v.x, k0v.y}, kl0[2] = {k0v.z, k0v.w};
            unsigned kh1[2] = {k1v.x, k1v.y}, kl1[2] = {k1v.z, k1v.w};

            mma16816(S0, ah, kh0, S0);
            mma16816(S0, al, kh0, S0);
            mma16816(S0, ah, kl0, S0);
            mma16816(S1, ah, kh1, S1);
            mma16816(S1, al, kh1, S1);
            mma16816(S1, ah, kl1, S1);

            unsigned pa[4];
            pa[0] = ex2h2(packh2(fminf(S0[0], SCLAMP), fminf(S0[1], SCLAMP)));
            pa[1] = ex2h2(packh2(fminf(S0[2], SCLAMP), fminf(S0[3], SCLAMP)));
            pa[2] = ex2h2(packh2(fminf(S1[0], SCLAMP), fminf(S1[1], SCLAMP)));
            pa[3] = ex2h2(packh2(fminf(S1[2], SCLAMP), fminf(S1[3], SCLAMP)));

            uint2 vv = *(const uint2*)&Vb[(l >> 2) * 72 + (c16 >> 4) * 8 + c4 * 2];
            unsigned vh[2] = {vv.x, vv.y};

            mma16816h(O0, pa, vh, O0);
            mma16816h(La, pa, bones, La);
        }

        if (it + 1 < NIT) sts_tile(bb ^ 1);
        __syncthreads();
    }

    const size_t pbase = (size_t)(kz * BH_ + bh) * N_;
    float* o0 = d_patt + (pbase + qr0) * 8 + 2 * c4;
    float* o1 = d_patt + (pbase + qr1) * 8 + 2 * c4;
    o0[0] = O0[0]; o0[1] = O0[1];
    o1[0] = O0[2]; o1[1] = O0[3];
    if (c4 == 0) {
        d_pl[pbase + qr0] = La[0];
        d_pl[pbase + qr1] = La[2];
    }
}

// =====================================================================
// Kernel C: fused split-combine + op-projection + dilated convs + BN +
//           residual LN + horizon MLP. 32 nodes/block (8 warps x 4).
// =====================================================================
__global__ void __launch_bounds__(256)
tail_kernel(const float* __restrict__ op_w, const float* __restrict__ op_b,
            const float* __restrict__ tc0_w, const float* __restrict__ tc0_b,
            const float* __restrict__ tc1_w, const float* __restrict__ tc1_b,
            const float* __restrict__ bn_g, const float* __restrict__ bn_b,
            const float* __restrict__ ln_g, const float* __restrict__ ln_b,
            const float* __restrict__ h1_w, const float* __restrict__ h1_b,
            const float* __restrict__ hln_g, const float* __restrict__ hln_b,
            const float* __restrict__ h2_w, const float* __restrict__ h2_b,
            float* __restrict__ out)
{
    __shared__ float ss[36 * 32];
    __shared__ float at[36 * 33];
    __shared__ float ow[32 * 33];
    __shared__ float tw0[96 * 33];
    __shared__ float tw1[96 * 33];

    const int tid = threadIdx.x;
    const int blk = blockIdx.x;
    const int b   = blk >> 7;
    const int n0  = (blk & 127) << 5;

    for (int idx = tid; idx < 3072; idx += 256) {
        int co = idx / 96, rem = idx % 96;
        tw0[rem * 33 + co] = tc0_w[idx];
        tw1[rem * 33 + co] = tc1_w[idx];
    }
    for (int idx = tid; idx < 1024; idx += 256) {
        int o = idx >> 5, i = idx & 31;
        ow[i * 33 + o] = op_w[idx];
    }
    for (int idx = tid; idx < 1152; idx += 256) {
        int rr = idx >> 5, c = idx & 31;
        int gn = n0 - 2 + rr;
        float val = 0.f;
        if (gn >= 0 && gn < N_) {
            int head = c >> 3, e = c & 7;
            float num = 0.f, den = 0.f;
#pragma unroll
            for (int s = 0; s < KSPLIT; s++) {
                size_t r = ((size_t)(s * BH_ + b * 4 + head) * N_ + gn);
                num += d_patt[r * 8 + e];
                den += d_pl[r];
            }
            val = __fdividef(num, den);
        }
        at[rr * 33 + c] = val;
    }
    __syncthreads();

    const int w = tid >> 5, lane = tid & 31;

    for (int r = w; r < 36; r += 8) {
        int gn = n0 - 2 + r;
        float o = 0.f;
        if (gn >= 0 && gn < N_) {
            o = __ldg(op_b + lane);
#pragma unroll
            for (int i = 0; i < 32; i++)
                o += at[r * 33 + i] * ow[i * 33 + lane];
        }
        ss[r * 32 + lane] = o;
    }
    __syncthreads();

    const float b0 = __ldg(tc0_b + lane), b1 = __ldg(tc1_b + lane);

    float v0[4], v1[4];
#pragma unroll
    for (int t = 0; t < 4; t++) { v0[t] = b0; v1[t] = b1; }

#pragma unroll 4
    for (int ci = 0; ci < 32; ci++) {
        float w00 = tw0[(ci * 3 + 0) * 33 + lane];
        float w01 = tw0[(ci * 3 + 1) * 33 + lane];
        float w02 = tw0[(ci * 3 + 2) * 33 + lane];
        float w10 = tw1[(ci * 3 + 0) * 33 + lane];
        float w11 = tw1[(ci * 3 + 1) * 33 + lane];
        float w12 = tw1[(ci * 3 + 2) * 33 + lane];
        float s[8];
#pragma unroll
        for (int j = 0; j < 8; j++) s[j] = ss[(w * 4 + j) * 32 + ci];
#pragma unroll
        for (int t = 0; t < 4; t++) {
            v0[t] += s[t + 1] * w00 + s[t + 2] * w01 + s[t + 3] * w02;
            v1[t] += s[t]     * w10 + s[t + 2] * w11 + s[t + 4] * w12;
        }
    }

    const float bs = __ldg(bn_g + lane) * rsqrtf(1.f + 1e-5f);
    const float bb = __ldg(bn_b + lane);
    const float lng = __ldg(ln_g + lane), lnb = __ldg(ln_b + lane);

#pragma unroll
    for (int t = 0; t < 4; t++) {
        const int lr = w * 4 + t + 2;
        const int n = n0 + w * 4 + t;
        float y0 = fmaxf(v0[t] * bs + bb, 0.f);
        float y1 = fmaxf(v1[t] * bs + bb, 0.f);
        float resid = 0.5f * (y0 + y1) + ss[lr * 32 + lane];

        float sum = resid, sq = resid * resid;
#pragma unroll
        for (int off = 16; off; off >>= 1) {
            sum += __shfl_xor_sync(0xffffffffu, sum, off);
            sq  += __shfl_xor_sync(0xffffffffu, sq, off);
        }
        float mu = sum * (1.f / 32.f);
        float var = sq * (1.f / 32.f) - mu * mu;
        float rstd = rsqrtf(var + 1e-5f);
        float tout = (resid - mu) * rstd * lng + lnb;

        float hj[8];
#pragma unroll
        for (int j = 0; j < 8; j++) hj[j] = tout * __ldg(h1_w + j * 32 + lane);
#pragma unroll
        for (int j = 0; j < 8; j++)
#pragma unroll
            for (int off = 16; off; off >>= 1)
                hj[j] += __shfl_xor_sync(0xffffffffu, hj[j], off);

        float hsum = 0.f;
#pragma unroll
        for (int j = 0; j < 8; j++) { hj[j] += __ldg(h1_b + j); hsum += hj[j]; }
        float hmu = hsum * (1.f / 8.f);
        float hsq = 0.f;
#pragma unroll
        for (int j = 0; j < 8; j++) { float dd = hj[j] - hmu; hsq += dd * dd; }
        float hrstd = rsqrtf(hsq * (1.f / 8.f) + 1e-5f);
        float hh[8];
#pragma unroll
        for (int j = 0; j < 8; j++)
            hh[j] = fmaxf((hj[j] - hmu) * hrstd * __ldg(hln_g + j) + __ldg(hln_b + j), 0.f);

        if (lane < HOR_) {
            float p = __ldg(h2_b + lane);
#pragma unroll
            for (int j = 0; j < 8; j++) p += hh[j] * __ldg(h2_w + lane * 8 + j);
            out[(size_t)b * HOR_ * N_ + (size_t)lane * N_ + n] = p;
        }
    }
}

// =====================================================================
extern "C" void kernel_launch(void* const* d_in, const int* in_sizes, int n_in,
                              void* d_out, int out_size)
{
    const float* x      = (const float*)d_in[0];
    const float* fe_w   = (const float*)d_in[1];
    const float* fe_b   = (const float*)d_in[2];
    const float* fe_bng = (const float*)d_in[3];
    const float* fe_bnb = (const float*)d_in[4];
    const float* p1_w   = (const float*)d_in[5];
    const float* p1_b   = (const float*)d_in[6];
    const float* p2_w   = (const float*)d_in[7];
    const float* p2_b   = (const float*)d_in[8];
    const float* qkv_w  = (const float*)d_in[9];
    const float* qkv_b  = (const float*)d_in[10];
    const float* op_w   = (const float*)d_in[11];
    const float* op_b   = (const float*)d_in[12];
    const float* u      = (const float*)d_in[13];
    const float* v      = (const float*)d_in[14];
    const float* tc0_w  = (const float*)d_in[15];
    const float* tc0_b  = (const float*)d_in[16];
    const float* tc1_w  = (const float*)d_in[17];
    const float* tc1_b  = (const float*)d_in[18];
    const float* t_bng  = (const float*)d_in[19];
    const float* t_bnb  = (const float*)d_in[20];
    const float* t_lng  = (const float*)d_in[21];
    const float* t_lnb  = (const float*)d_in[22];
    const float* h1_w   = (const float*)d_in[23];
    const float* h1_b   = (const float*)d_in[24];
    const float* h_lng  = (const float*)d_in[25];
    const float* h_lnb  = (const float*)d_in[26];
    const float* h2_w   = (const float*)d_in[27];
    const float* h2_b   = (const float*)d_in[28];
    float* out = (float*)d_out;

    feat_kernel<<<(B_ * N_) / 8, 256>>>(x, fe_w, fe_b, fe_bng, fe_bnb,
                                        p1_w, p1_b, p2_w, p2_b,
                                        qkv_w, qkv_b, u, v);

    dim3 agrid(N_ / 128, BH_, KSPLIT);      // (32, 8, 4) = 1024 blocks
    attn_kernel<<<agrid, 256>>>();

    tail_kernel<<<(B_ * N_) / 32, 256>>>(op_w, op_b,
                                         tc0_w, tc0_b, tc1_w, tc1_b,
                                         t_bng, t_bnb, t_lng, t_lnb,
                                         h1_w, h1_b, h_lng, h_lnb,
                                         h2_w, h2_b, out);
}